// round 1
// baseline (speedup 1.0000x reference)
#include <cuda_runtime.h>
#include <cstdint>
#include <cstddef>

#define XD   512
#define HID_ 1024
#define BB   64
#define TT   512
#define G4   4096
#define MROWS 32768   // BB*TT

typedef unsigned long long u64;

// ---------------- device scratch (static: no allocations allowed) ----------------
__device__ float g_Wx4[(size_t)XD * G4];          //   8 MB packed [k][g*H+j]
__device__ float g_Wh4[(size_t)HID_ * G4];        //  16 MB packed
__device__ float g_b4[G4];
__device__ float g_xproj[(size_t)MROWS * G4];     // 512 MB : X @ Wx (no bias)
__device__ float g_h[2][HID_ * BB];               // transposed h: [col][b], double buffered
__device__ unsigned g_bar_cnt;                    // zero-initialized; self-resetting barrier
__device__ volatile unsigned g_bar_phase;

// ---------------- packed fp32 helpers ----------------
__device__ __forceinline__ u64 splat2(float x) {
    u64 r; asm("mov.b64 %0, {%1, %1};" : "=l"(r) : "f"(x)); return r;
}
__device__ __forceinline__ void ffma2(u64& d, u64 a, u64 b) {
    asm("fma.rn.f32x2 %0, %1, %2, %0;" : "+l"(d) : "l"(a), "l"(b));
}
__device__ __forceinline__ float sigmoidf_(float x) { return 1.f / (1.f + __expf(-x)); }

// ---------------- kernel 0: pack weights gate-major ----------------
__global__ void pack_kernel(const float* __restrict__ Wxi, const float* __restrict__ Wxf,
                            const float* __restrict__ Wxo, const float* __restrict__ Wxz,
                            const float* __restrict__ Whi, const float* __restrict__ Whf,
                            const float* __restrict__ Who, const float* __restrict__ Whz,
                            const float* __restrict__ bi,  const float* __restrict__ bf,
                            const float* __restrict__ bo,  const float* __restrict__ bz) {
    int tid0 = blockIdx.x * blockDim.x + threadIdx.x;
    int stride = gridDim.x * blockDim.x;
    for (int idx = tid0; idx < XD * G4; idx += stride) {
        int k = idx >> 12, col = idx & 4095, g = col >> 10, j = col & 1023;
        const float* W = (g == 0) ? Wxi : (g == 1) ? Wxf : (g == 2) ? Wxo : Wxz;
        g_Wx4[idx] = W[k * HID_ + j];
    }
    for (int idx = tid0; idx < HID_ * G4; idx += stride) {
        int k = idx >> 12, col = idx & 4095, g = col >> 10, j = col & 1023;
        const float* W = (g == 0) ? Whi : (g == 1) ? Whf : (g == 2) ? Who : Whz;
        g_Wh4[idx] = W[k * HID_ + j];
    }
    for (int idx = tid0; idx < G4; idx += stride) {
        int g = idx >> 10, j = idx & 1023;
        const float* b = (g == 0) ? bi : (g == 1) ? bf : (g == 2) ? bo : bz;
        g_b4[idx] = b[j];
    }
}

// ---------------- kernel A: xproj = X @ Wx4  (128x128 tile SGEMM, f32x2) ----------------
__global__ __launch_bounds__(256) void xproj_kernel(const float* __restrict__ X) {
    __shared__ __align__(16) float As[16][128];   // [k][m] (transposed)
    __shared__ __align__(16) float Bs[16][128];   // [k][n]
    int tid = threadIdx.x;
    int mbase = blockIdx.y * 128;
    int nbase = blockIdx.x * 128;
    int tm = tid >> 4, tn = tid & 15;
    int m0 = tm * 8, n0 = tn * 8;

    u64 acc[8][4];
#pragma unroll
    for (int i = 0; i < 8; i++)
#pragma unroll
        for (int j = 0; j < 4; j++) acc[i][j] = 0ULL;

    for (int k0 = 0; k0 < XD; k0 += 16) {
#pragma unroll
        for (int r = 0; r < 2; r++) {                    // A tile: transpose into As[k][m]
            int idx = tid + r * 256;
            int m = idx >> 2, kq = (idx & 3) * 4;
            float4 v = *(const float4*)&X[(size_t)(mbase + m) * XD + k0 + kq];
            As[kq + 0][m] = v.x; As[kq + 1][m] = v.y; As[kq + 2][m] = v.z; As[kq + 3][m] = v.w;
        }
#pragma unroll
        for (int r = 0; r < 2; r++) {                    // B tile: direct copy
            int idx = tid + r * 256;
            int kk = idx >> 5, n = (idx & 31) * 4;
            *(float4*)&Bs[kk][n] = *(const float4*)&g_Wx4[(size_t)(k0 + kk) * G4 + nbase + n];
        }
        __syncthreads();
#pragma unroll
        for (int kk = 0; kk < 16; kk++) {
            float4 a0 = *(const float4*)&As[kk][m0];
            float4 a1 = *(const float4*)&As[kk][m0 + 4];
            ulonglong2 b01 = *(const ulonglong2*)&Bs[kk][n0];
            ulonglong2 b23 = *(const ulonglong2*)&Bs[kk][n0 + 4];
            float am[8] = {a0.x, a0.y, a0.z, a0.w, a1.x, a1.y, a1.z, a1.w};
#pragma unroll
            for (int i = 0; i < 8; i++) {
                u64 aa = splat2(am[i]);
                ffma2(acc[i][0], aa, b01.x);
                ffma2(acc[i][1], aa, b01.y);
                ffma2(acc[i][2], aa, b23.x);
                ffma2(acc[i][3], aa, b23.y);
            }
        }
        __syncthreads();
    }
#pragma unroll
    for (int i = 0; i < 8; i++) {
        size_t off = (size_t)(mbase + m0 + i) * G4 + nbase + n0;
        ulonglong2 s0; s0.x = acc[i][0]; s0.y = acc[i][1];
        ulonglong2 s1; s1.x = acc[i][2]; s1.y = acc[i][3];
        *(ulonglong2*)&g_xproj[off]     = s0;
        *(ulonglong2*)&g_xproj[off + 4] = s1;
    }
}

// ---------------- kernel B: persistent recurrence ----------------
#define NCTA 128
#define NC   8                 // h-cols per CTA -> 32 gate cols -> 16 packed pairs
#define NPC  16
#define PROW 40                // padded partial row (floats): bank-spread, 16B-aligned
#define SMEM_BYTES (HID_ * NPC * 8 + 8 * BB * PROW * 4 + 32 * 4)

__device__ __forceinline__ void grid_sync(unsigned& phase) {
    __threadfence();
    __syncthreads();
    if (threadIdx.x == 0) {
        unsigned arrived = atomicAdd(&g_bar_cnt, 1u) + 1u;
        if (arrived == gridDim.x) {
            g_bar_cnt = 0;           // self-reset before release
            __threadfence();
            g_bar_phase = phase + 1u;
        } else {
            while (g_bar_phase == phase) __nanosleep(64);
        }
        phase = phase + 1u;
        __threadfence();
    }
    __syncthreads();
}

__global__ __launch_bounds__(256, 1) void lstm_kernel(float* __restrict__ out) {
    extern __shared__ __align__(16) char smem_raw[];
    u64*   Ws     = (u64*)smem_raw;                       // [1024][16] f32x2 pairs
    float* part   = (float*)(smem_raw + HID_ * NPC * 8);  // [8][64][PROW]
    float* bias_s = part + 8 * BB * PROW;                 // [32]

    int tid = threadIdx.x;
    int j0  = blockIdx.x * NC;

    // Load Wh slice into SMEM (once): pc = g*4+pp -> cols (g*1024 + j0 + 2pp, +1)
    for (int idx = tid; idx < HID_ * NPC; idx += 256) {
        int k = idx >> 4, pc = idx & 15;
        int g = pc >> 2, pp = pc & 3;
        float2 v = *(const float2*)&g_Wh4[(size_t)k * G4 + g * HID_ + j0 + pp * 2];
        Ws[idx] = reinterpret_cast<const u64&>(v);
    }
    if (tid < 32) {
        int g = tid >> 3, j = tid & 7;
        bias_s[tid] = g_b4[g * HID_ + j0 + j];
    }
    // zero our slice of h buffer 0
    for (int idx = tid; idx < NC * BB; idx += 256)
        g_h[0][(j0 + (idx >> 6)) * BB + (idx & 63)] = 0.f;

    unsigned phase = 0;
    if (tid == 0) phase = g_bar_phase;   // resume phase across graph replays

    // GEMM-role decomposition: warp = k-slice
    int ks = tid >> 5;
    int bg = (tid >> 2) & 7;
    int pg = tid & 3;
    int b0 = bg * 8;
    int pc0 = pg * 4;
    int kbase = ks * 128;

    // activation-role decomposition (fixed owner -> c stays in registers)
    int p_b0 = tid >> 3;         // 0..31
    int p_j  = tid & 7;
    int p_b1 = p_b0 + 32;        // 32..63
    float c0 = 0.f, c1 = 0.f;

    grid_sync(phase);            // h zeros visible everywhere

    for (int t = 0; t < TT; t++) {
        const float* hprev = g_h[t & 1];
        float* hnext = g_h[(t + 1) & 1];

        // prefetch xproj for our two activation outputs (hides DRAM latency)
        float xp0[4], xp1[4];
#pragma unroll
        for (int g = 0; g < 4; g++) {
            xp0[g] = g_xproj[(size_t)(p_b0 * TT + t) * G4 + g * HID_ + j0 + p_j];
            xp1[g] = g_xproj[(size_t)(p_b1 * TT + t) * G4 + g * HID_ + j0 + p_j];
        }

        u64 acc[8][4];
#pragma unroll
        for (int i = 0; i < 8; i++)
#pragma unroll
            for (int j = 0; j < 4; j++) acc[i][j] = 0ULL;

        const float* hrow = hprev + kbase * BB + b0;
        const u64*   wrow = Ws + kbase * NPC + pc0;
#pragma unroll 4
        for (int kk = 0; kk < 128; kk++) {
            float4 h0v = *(const float4*)(hrow);
            float4 h1v = *(const float4*)(hrow + 4);
            ulonglong2 w01 = *(const ulonglong2*)(wrow);
            ulonglong2 w23 = *(const ulonglong2*)(wrow + 2);
            float hm[8] = {h0v.x, h0v.y, h0v.z, h0v.w, h1v.x, h1v.y, h1v.z, h1v.w};
#pragma unroll
            for (int i = 0; i < 8; i++) {
                u64 aa = splat2(hm[i]);
                ffma2(acc[i][0], aa, w01.x);
                ffma2(acc[i][1], aa, w01.y);
                ffma2(acc[i][2], aa, w23.x);
                ffma2(acc[i][3], aa, w23.y);
            }
            hrow += BB;
            wrow += NPC;
        }
        // write partials: gc = pc*2 (+1)
#pragma unroll
        for (int i = 0; i < 8; i++) {
            float* dst = part + (size_t)(ks * BB + b0 + i) * PROW + pc0 * 2;
            ulonglong2 s0; s0.x = acc[i][0]; s0.y = acc[i][1];
            ulonglong2 s1; s1.x = acc[i][2]; s1.y = acc[i][3];
            *(ulonglong2*)dst       = s0;
            *(ulonglong2*)(dst + 4) = s1;
        }
        __syncthreads();

        // activation phase: 2 (b, j) outputs per thread
        float ga[4], gb[4];
#pragma unroll
        for (int g = 0; g < 4; g++) {
            float sa = xp0[g] + bias_s[g * 8 + p_j];
            float sb = xp1[g] + bias_s[g * 8 + p_j];
#pragma unroll
            for (int s = 0; s < 8; s++) {
                sa += part[(size_t)(s * BB + p_b0) * PROW + g * 8 + p_j];
                sb += part[(size_t)(s * BB + p_b1) * PROW + g * 8 + p_j];
            }
            ga[g] = sa; gb[g] = sb;
        }
        {
            float ig = sigmoidf_(ga[0]), fg = sigmoidf_(ga[1]);
            float og = sigmoidf_(ga[2]), zg = tanhf(ga[3]);
            c0 = ig * zg + fg * c0;
            float hv = og * tanhf(c0);
            hnext[(j0 + p_j) * BB + p_b0] = hv;
            out[((size_t)p_b0 * TT + t) * HID_ + j0 + p_j] = hv;
        }
        {
            float ig = sigmoidf_(gb[0]), fg = sigmoidf_(gb[1]);
            float og = sigmoidf_(gb[2]), zg = tanhf(gb[3]);
            c1 = ig * zg + fg * c1;
            float hv = og * tanhf(c1);
            hnext[(j0 + p_j) * BB + p_b1] = hv;
            out[((size_t)p_b1 * TT + t) * HID_ + j0 + p_j] = hv;
        }
        grid_sync(phase);
    }
}

// ---------------- launch ----------------
extern "C" void kernel_launch(void* const* d_in, const int* in_sizes, int n_in,
                              void* d_out, int out_size) {
    const float* X   = (const float*)d_in[0];
    const float* Whi = (const float*)d_in[1];
    const float* Wxi = (const float*)d_in[2];
    const float* bi  = (const float*)d_in[3];
    const float* Whf = (const float*)d_in[4];
    const float* Wxf = (const float*)d_in[5];
    const float* bf  = (const float*)d_in[6];
    const float* Who = (const float*)d_in[7];
    const float* Wxo = (const float*)d_in[8];
    const float* bo  = (const float*)d_in[9];
    const float* Whz = (const float*)d_in[10];
    const float* Wxz = (const float*)d_in[11];
    const float* bz  = (const float*)d_in[12];

    pack_kernel<<<1024, 256>>>(Wxi, Wxf, Wxo, Wxz, Whi, Whf, Who, Whz, bi, bf, bo, bz);

    dim3 gA(32, 256);   // N tiles x M tiles
    xproj_kernel<<<gA, 256>>>(X);

    cudaFuncSetAttribute(lstm_kernel, cudaFuncAttributeMaxDynamicSharedMemorySize, SMEM_BYTES);
    lstm_kernel<<<NCTA, 256, SMEM_BYTES>>>((float*)d_out);
}

// round 2
// speedup vs baseline: 1.0014x; 1.0014x over previous
#include <cuda_runtime.h>
#include <cstdint>
#include <cstddef>

#define XD   512
#define HID_ 1024
#define BB   64
#define TT   512
#define G4   4096
#define MROWS 32768   // BB*TT

typedef unsigned long long u64;

// ---------------- device scratch (static: no allocations allowed) ----------------
__device__ float g_Wx4[(size_t)XD * G4];          //   8 MB packed [k][g*H+j]
__device__ float g_Wh4[(size_t)HID_ * G4];        //  16 MB packed
__device__ float g_b4[G4];
__device__ float g_xproj[(size_t)MROWS * G4];     // 512 MB : X @ Wx (no bias)
__device__ float g_h[2][HID_ * BB];               // transposed h: [col][b], double buffered
__device__ unsigned g_bar_cnt;                    // zero-initialized; self-resetting barrier
__device__ volatile unsigned g_bar_phase;

// ---------------- packed fp32 helpers ----------------
__device__ __forceinline__ u64 splat2(float x) {
    u64 r; asm("mov.b64 %0, {%1, %1};" : "=l"(r) : "f"(x)); return r;
}
__device__ __forceinline__ void ffma2(u64& d, u64 a, u64 b) {
    asm("fma.rn.f32x2 %0, %1, %2, %0;" : "+l"(d) : "l"(a), "l"(b));
}
__device__ __forceinline__ float sigmoidf_(float x) { return 1.f / (1.f + __expf(-x)); }

// ---------------- kernel 0: pack weights gate-major ----------------
__global__ void pack_kernel(const float* __restrict__ Wxi, const float* __restrict__ Wxf,
                            const float* __restrict__ Wxo, const float* __restrict__ Wxz,
                            const float* __restrict__ Whi, const float* __restrict__ Whf,
                            const float* __restrict__ Who, const float* __restrict__ Whz,
                            const float* __restrict__ bi,  const float* __restrict__ bf,
                            const float* __restrict__ bo,  const float* __restrict__ bz) {
    int tid0 = blockIdx.x * blockDim.x + threadIdx.x;
    int stride = gridDim.x * blockDim.x;
    for (int idx = tid0; idx < XD * G4; idx += stride) {
        int k = idx >> 12, col = idx & 4095, g = col >> 10, j = col & 1023;
        const float* W = (g == 0) ? Wxi : (g == 1) ? Wxf : (g == 2) ? Wxo : Wxz;
        g_Wx4[idx] = W[k * HID_ + j];
    }
    for (int idx = tid0; idx < HID_ * G4; idx += stride) {
        int k = idx >> 12, col = idx & 4095, g = col >> 10, j = col & 1023;
        const float* W = (g == 0) ? Whi : (g == 1) ? Whf : (g == 2) ? Who : Whz;
        g_Wh4[idx] = W[k * HID_ + j];
    }
    for (int idx = tid0; idx < G4; idx += stride) {
        int g = idx >> 10, j = idx & 1023;
        const float* b = (g == 0) ? bi : (g == 1) ? bf : (g == 2) ? bo : bz;
        g_b4[idx] = b[j];
    }
}

// ---------------- kernel A: xproj = X @ Wx4  (128x128 tile SGEMM, f32x2) ----------------
__global__ __launch_bounds__(256) void xproj_kernel(const float* __restrict__ X) {
    __shared__ __align__(16) float As[16][128];   // [k][m] (transposed)
    __shared__ __align__(16) float Bs[16][128];   // [k][n]
    int tid = threadIdx.x;
    int mbase = blockIdx.y * 128;
    int nbase = blockIdx.x * 128;
    int tm = tid >> 4, tn = tid & 15;
    int m0 = tm * 8, n0 = tn * 8;

    u64 acc[8][4];
#pragma unroll
    for (int i = 0; i < 8; i++)
#pragma unroll
        for (int j = 0; j < 4; j++) acc[i][j] = 0ULL;

    for (int k0 = 0; k0 < XD; k0 += 16) {
#pragma unroll
        for (int r = 0; r < 2; r++) {                    // A tile: transpose into As[k][m]
            int idx = tid + r * 256;
            int m = idx >> 2, kq = (idx & 3) * 4;
            float4 v = *(const float4*)&X[(size_t)(mbase + m) * XD + k0 + kq];
            As[kq + 0][m] = v.x; As[kq + 1][m] = v.y; As[kq + 2][m] = v.z; As[kq + 3][m] = v.w;
        }
#pragma unroll
        for (int r = 0; r < 2; r++) {                    // B tile: direct copy
            int idx = tid + r * 256;
            int kk = idx >> 5, n = (idx & 31) * 4;
            *(float4*)&Bs[kk][n] = *(const float4*)&g_Wx4[(size_t)(k0 + kk) * G4 + nbase + n];
        }
        __syncthreads();
#pragma unroll
        for (int kk = 0; kk < 16; kk++) {
            float4 a0 = *(const float4*)&As[kk][m0];
            float4 a1 = *(const float4*)&As[kk][m0 + 4];
            ulonglong2 b01 = *(const ulonglong2*)&Bs[kk][n0];
            ulonglong2 b23 = *(const ulonglong2*)&Bs[kk][n0 + 4];
            float am[8] = {a0.x, a0.y, a0.z, a0.w, a1.x, a1.y, a1.z, a1.w};
#pragma unroll
            for (int i = 0; i < 8; i++) {
                u64 aa = splat2(am[i]);
                ffma2(acc[i][0], aa, b01.x);
                ffma2(acc[i][1], aa, b01.y);
                ffma2(acc[i][2], aa, b23.x);
                ffma2(acc[i][3], aa, b23.y);
            }
        }
        __syncthreads();
    }
#pragma unroll
    for (int i = 0; i < 8; i++) {
        size_t off = (size_t)(mbase + m0 + i) * G4 + nbase + n0;
        ulonglong2 s0; s0.x = acc[i][0]; s0.y = acc[i][1];
        ulonglong2 s1; s1.x = acc[i][2]; s1.y = acc[i][3];
        *(ulonglong2*)&g_xproj[off]     = s0;
        *(ulonglong2*)&g_xproj[off + 4] = s1;
    }
}

// ---------------- kernel B: persistent recurrence ----------------
#define NCTA 128
#define NC   8                 // h-cols per CTA -> 32 gate cols -> 16 packed pairs
#define NPC  16
#define PROW 40                // padded partial row (floats): bank-spread, 16B-aligned
#define SMEM_BYTES (HID_ * NPC * 8 + 8 * BB * PROW * 4 + 32 * 4)

__device__ __forceinline__ void grid_sync(unsigned& phase) {
    __threadfence();
    __syncthreads();
    if (threadIdx.x == 0) {
        unsigned arrived = atomicAdd(&g_bar_cnt, 1u) + 1u;
        if (arrived == gridDim.x) {
            g_bar_cnt = 0;           // self-reset before release
            __threadfence();
            g_bar_phase = phase + 1u;
        } else {
            while (g_bar_phase == phase) __nanosleep(64);
        }
        phase = phase + 1u;
        __threadfence();
    }
    __syncthreads();
}

__global__ __launch_bounds__(256, 1) void lstm_kernel(float* __restrict__ out) {
    extern __shared__ __align__(16) char smem_raw[];
    u64*   Ws     = (u64*)smem_raw;                       // [1024][16] f32x2 pairs
    float* part   = (float*)(smem_raw + HID_ * NPC * 8);  // [8][64][PROW]
    float* bias_s = part + 8 * BB * PROW;                 // [32]

    int tid = threadIdx.x;
    int j0  = blockIdx.x * NC;

    // Load Wh slice into SMEM (once): pc = g*4+pp -> cols (g*1024 + j0 + 2pp, +1)
    for (int idx = tid; idx < HID_ * NPC; idx += 256) {
        int k = idx >> 4, pc = idx & 15;
        int g = pc >> 2, pp = pc & 3;
        float2 v = *(const float2*)&g_Wh4[(size_t)k * G4 + g * HID_ + j0 + pp * 2];
        Ws[idx] = reinterpret_cast<const u64&>(v);
    }
    if (tid < 32) {
        int g = tid >> 3, j = tid & 7;
        bias_s[tid] = g_b4[g * HID_ + j0 + j];
    }
    // zero our slice of h buffer 0
    for (int idx = tid; idx < NC * BB; idx += 256)
        g_h[0][(j0 + (idx >> 6)) * BB + (idx & 63)] = 0.f;

    unsigned phase = 0;
    if (tid == 0) phase = g_bar_phase;   // resume phase across graph replays

    // GEMM-role decomposition: warp = k-slice
    int ks = tid >> 5;
    int bg = (tid >> 2) & 7;
    int pg = tid & 3;
    int b0 = bg * 8;
    int pc0 = pg * 4;
    int kbase = ks * 128;

    // activation-role decomposition (fixed owner -> c stays in registers)
    int p_b0 = tid >> 3;         // 0..31
    int p_j  = tid & 7;
    int p_b1 = p_b0 + 32;        // 32..63
    float c0 = 0.f, c1 = 0.f;

    grid_sync(phase);            // h zeros visible everywhere

    for (int t = 0; t < TT; t++) {
        const float* hprev = g_h[t & 1];
        float* hnext = g_h[(t + 1) & 1];

        // prefetch xproj for our two activation outputs (hides DRAM latency)
        float xp0[4], xp1[4];
#pragma unroll
        for (int g = 0; g < 4; g++) {
            xp0[g] = g_xproj[(size_t)(p_b0 * TT + t) * G4 + g * HID_ + j0 + p_j];
            xp1[g] = g_xproj[(size_t)(p_b1 * TT + t) * G4 + g * HID_ + j0 + p_j];
        }

        u64 acc[8][4];
#pragma unroll
        for (int i = 0; i < 8; i++)
#pragma unroll
            for (int j = 0; j < 4; j++) acc[i][j] = 0ULL;

        const float* hrow = hprev + kbase * BB + b0;
        const u64*   wrow = Ws + kbase * NPC + pc0;
#pragma unroll 4
        for (int kk = 0; kk < 128; kk++) {
            float4 h0v = *(const float4*)(hrow);
            float4 h1v = *(const float4*)(hrow + 4);
            ulonglong2 w01 = *(const ulonglong2*)(wrow);
            ulonglong2 w23 = *(const ulonglong2*)(wrow + 2);
            float hm[8] = {h0v.x, h0v.y, h0v.z, h0v.w, h1v.x, h1v.y, h1v.z, h1v.w};
#pragma unroll
            for (int i = 0; i < 8; i++) {
                u64 aa = splat2(hm[i]);
                ffma2(acc[i][0], aa, w01.x);
                ffma2(acc[i][1], aa, w01.y);
                ffma2(acc[i][2], aa, w23.x);
                ffma2(acc[i][3], aa, w23.y);
            }
            hrow += BB;
            wrow += NPC;
        }
        // write partials: gc = pc*2 (+1)
#pragma unroll
        for (int i = 0; i < 8; i++) {
            float* dst = part + (size_t)(ks * BB + b0 + i) * PROW + pc0 * 2;
            ulonglong2 s0; s0.x = acc[i][0]; s0.y = acc[i][1];
            ulonglong2 s1; s1.x = acc[i][2]; s1.y = acc[i][3];
            *(ulonglong2*)dst       = s0;
            *(ulonglong2*)(dst + 4) = s1;
        }
        __syncthreads();

        // activation phase: 2 (b, j) outputs per thread
        float ga[4], gb[4];
#pragma unroll
        for (int g = 0; g < 4; g++) {
            float sa = xp0[g] + bias_s[g * 8 + p_j];
            float sb = xp1[g] + bias_s[g * 8 + p_j];
#pragma unroll
            for (int s = 0; s < 8; s++) {
                sa += part[(size_t)(s * BB + p_b0) * PROW + g * 8 + p_j];
                sb += part[(size_t)(s * BB + p_b1) * PROW + g * 8 + p_j];
            }
            ga[g] = sa; gb[g] = sb;
        }
        {
            float ig = sigmoidf_(ga[0]), fg = sigmoidf_(ga[1]);
            float og = sigmoidf_(ga[2]), zg = tanhf(ga[3]);
            c0 = ig * zg + fg * c0;
            float hv = og * tanhf(c0);
            hnext[(j0 + p_j) * BB + p_b0] = hv;
            out[((size_t)p_b0 * TT + t) * HID_ + j0 + p_j] = hv;
        }
        {
            float ig = sigmoidf_(gb[0]), fg = sigmoidf_(gb[1]);
            float og = sigmoidf_(gb[2]), zg = tanhf(gb[3]);
            c1 = ig * zg + fg * c1;
            float hv = og * tanhf(c1);
            hnext[(j0 + p_j) * BB + p_b1] = hv;
            out[((size_t)p_b1 * TT + t) * HID_ + j0 + p_j] = hv;
        }
        grid_sync(phase);
    }
}

// ---------------- launch ----------------
extern "C" void kernel_launch(void* const* d_in, const int* in_sizes, int n_in,
                              void* d_out, int out_size) {
    const float* X   = (const float*)d_in[0];
    const float* Whi = (const float*)d_in[1];
    const float* Wxi = (const float*)d_in[2];
    const float* bi  = (const float*)d_in[3];
    const float* Whf = (const float*)d_in[4];
    const float* Wxf = (const float*)d_in[5];
    const float* bf  = (const float*)d_in[6];
    const float* Who = (const float*)d_in[7];
    const float* Wxo = (const float*)d_in[8];
    const float* bo  = (const float*)d_in[9];
    const float* Whz = (const float*)d_in[10];
    const float* Wxz = (const float*)d_in[11];
    const float* bz  = (const float*)d_in[12];

    pack_kernel<<<1024, 256>>>(Wxi, Wxf, Wxo, Wxz, Whi, Whf, Who, Whz, bi, bf, bo, bz);

    dim3 gA(32, 256);   // N tiles x M tiles
    xproj_kernel<<<gA, 256>>>(X);

    cudaFuncSetAttribute(lstm_kernel, cudaFuncAttributeMaxDynamicSharedMemorySize, SMEM_BYTES);
    lstm_kernel<<<NCTA, 256, SMEM_BYTES>>>((float*)d_out);
}